// round 15
// baseline (speedup 1.0000x reference)
#include <cuda_runtime.h>
#include <cuda_fp16.h>
#include <cstdint>

#define BB 4
#define NN 160
#define DD 64
#define ZIc 64
#define ZEc 64
#define LL 4
#define LEc 8
#define H1 128
#define H2 64
#define ST 68   // s_h row stride in 32-bit words (64 data + 4 pad)

// ---------------- device scratch (allocation-free) ----------------
__device__ uint32_t g_u2i[BB * NN * 64];            // intra u  = pi + bi1
__device__ uint32_t g_pj2i[BB * NN * 64];           // intra pj
__device__ uint32_t g_pj2l[BB * NN * 64];           // inter pj (qj)
__device__ uint32_t g_u2l[BB * LL * NN * 64];       // inter u  = qi + ql + bl1

__device__ __forceinline__ uint32_t h2u(__half2 h) {
    return *reinterpret_cast<uint32_t*>(&h);
}
__device__ __forceinline__ __half2 u2h(uint32_t u) {
    return *reinterpret_cast<__half2*>(&u);
}

__device__ __forceinline__ void mma_f16(float& d0, float& d1, float& d2, float& d3,
                                        uint32_t a0, uint32_t a1, uint32_t a2, uint32_t a3,
                                        uint32_t b0, uint32_t b1) {
    asm volatile(
        "mma.sync.aligned.m16n8k16.row.col.f32.f16.f16.f32 "
        "{%0,%1,%2,%3}, {%4,%5,%6,%7}, {%8,%9}, {%0,%1,%2,%3};"
        : "+f"(d0), "+f"(d1), "+f"(d2), "+f"(d3)
        : "r"(a0), "r"(a1), "r"(a2), "r"(a3), "r"(b0), "r"(b1));
}

__device__ __forceinline__ void ldmx4(uint32_t& r0, uint32_t& r1,
                                      uint32_t& r2, uint32_t& r3, uint32_t addr) {
    asm volatile(
        "ldmatrix.sync.aligned.m8n8.x4.shared.b16 {%0,%1,%2,%3}, [%4];"
        : "=r"(r0), "=r"(r1), "=r"(r2), "=r"(r3) : "r"(addr));
}

// ---------------------------------------------------------------------------
// Kernel 1: projections + half2 packing. Block = (b, 4 n's), 128 threads (k).
// W1 columns loaded ONCE per block, reused for 4 n's; z-projections are
// per-block scalars. Emits u2i, pj2i, pj2l, u2l[l] as half2 words.
// ---------------------------------------------------------------------------
__global__ void proj_kernel(const float* __restrict__ ne,
                            const float* __restrict__ zi,
                            const float* __restrict__ ze,
                            const float* __restrict__ lag,
                            const float* __restrict__ Wi1,
                            const float* __restrict__ bi1,
                            const float* __restrict__ Wl1,
                            const float* __restrict__ bl1)
{
    __shared__ float s_ne[4][DD], s_zi[ZIc], s_ze[ZEc];
    __shared__ float s_pack[4][7][H1];
    const int bid = blockIdx.x;            // b*(NN/4) + ng
    const int b   = bid / (NN / 4);
    const int n0  = (bid % (NN / 4)) * 4;
    const int k   = threadIdx.x;           // 0..127

    for (int t = k; t < 4 * DD; t += H1)
        s_ne[t >> 6][t & 63] = ne[(b * NN + n0 + (t >> 6)) * DD + (t & 63)];
    if (k < ZIc) s_zi[k] = zi[b * ZIc + k];
    if (k < ZEc) s_ze[k] = ze[b * ZEc + k];
    __syncthreads();

    float api[4], apj[4], aqi[4], aqj[4];
    #pragma unroll
    for (int n = 0; n < 4; n++) { api[n] = 0.f; apj[n] = 0.f; aqi[n] = 0.f; aqj[n] = 0.f; }

    #pragma unroll 4
    for (int d = 0; d < DD; d++) {
        const float wa = Wi1[d * H1 + k];
        const float wb = Wi1[(DD + d) * H1 + k];
        const float va = Wl1[d * H1 + k];
        const float vb = Wl1[(DD + d) * H1 + k];
        #pragma unroll
        for (int n = 0; n < 4; n++) {
            const float nd = s_ne[n][d];
            api[n] += nd * wa;
            apj[n] += nd * wb;
            aqi[n] += nd * va;
            aqj[n] += nd * vb;
        }
    }

    float pz = bi1[k], qz = bl1[k];
    #pragma unroll 4
    for (int z = 0; z < ZIc; z++) {
        pz += s_zi[z] * Wi1[(2 * DD + z) * H1 + k];
        qz += s_ze[z] * Wl1[(2 * DD + z) * H1 + k];
    }

    float ql[LL];
    #pragma unroll
    for (int l = 0; l < LL; l++) {
        float a = 0.f;
        #pragma unroll
        for (int e = 0; e < LEc; e++)
            a += lag[l * LEc + e] * Wl1[(2 * DD + ZEc + e) * H1 + k];
        ql[l] = a;
    }

    #pragma unroll
    for (int n = 0; n < 4; n++) {
        s_pack[n][0][k] = api[n] + pz;
        s_pack[n][1][k] = apj[n];
        s_pack[n][2][k] = aqj[n];
        #pragma unroll
        for (int l = 0; l < LL; l++)
            s_pack[n][3 + l][k] = aqi[n] + qz + ql[l];
    }
    __syncthreads();

    for (int idx = k; idx < 4 * 7 * 64; idx += H1) {
        const int n   = idx / (7 * 64);
        const int row = (idx >> 6) % 7;
        const int c   = idx & 63;
        const int gn  = b * NN + n0 + n;
        const uint32_t v = h2u(__floats2half2_rn(s_pack[n][row][2 * c],
                                                 s_pack[n][row][2 * c + 1]));
        if (row == 0)      g_u2i[gn * 64 + c] = v;
        else if (row == 1) g_pj2i[gn * 64 + c] = v;
        else if (row == 2) g_pj2l[gn * 64 + c] = v;
        else {
            const int l = row - 3;
            g_u2l[((b * LL + l) * NN + (n0 + n)) * 64 + c] = v;
        }
    }
}

// ---------------------------------------------------------------------------
// Kernel 2: fp16 mma.sync pairwise MLP, pipelined double-buffered s_h.
// Block = one (b,[l]) x 4 i's, 256 thr = 8 warps.
//   warp: mg = wid&1 (m-half), jg = wid>>1 (40 j -> 5 n-tiles).
// Per n-tile: 4 ldmatrix.x4 hoisted upfront (latency overlapped), 16 HMMA,
// fused epilogue. Phase A(i+1) overlaps MMA(i).
// ---------------------------------------------------------------------------
extern __shared__ uint32_t smemw[];

__global__ __launch_bounds__(256, 2) void pair_mma_kernel(
    const float* __restrict__ Wi2, const float* __restrict__ bi2,
    const float* __restrict__ Wi3, const float* __restrict__ bi3,
    const float* __restrict__ Wl2, const float* __restrict__ bl2,
    const float* __restrict__ Wl3, const float* __restrict__ bl3,
    float* __restrict__ out)
{
    uint32_t* s_h0   = smemw;                       // NN*ST words
    uint32_t* s_h1   = smemw + NN * ST;             // NN*ST words
    float*    s_part = (float*)(smemw + 2 * NN * ST);  // [4][2][NN]

    const int tid  = threadIdx.x;
    const int wid  = tid >> 5;
    const int lane = tid & 31;
    const int bid  = blockIdx.x;

    const bool intra = (bid < BB * (NN / 4));
    int b, l = 0, i0;
    const float *W2, *b2, *W3, *b3p;
    const uint32_t *pj2, *u2base;
    if (intra) {
        b  = bid / (NN / 4);
        i0 = (bid % (NN / 4)) * 4;
        W2 = Wi2; b2 = bi2; W3 = Wi3; b3p = bi3;
        pj2 = g_pj2i + b * NN * 64;
        u2base = g_u2i + b * NN * 64;
    } else {
        const int e = bid - BB * (NN / 4);
        b = e / (LL * (NN / 4));
        const int r = e % (LL * (NN / 4));
        l  = r / (NN / 4);
        i0 = (r % (NN / 4)) * 4;
        W2 = Wl2; b2 = bl2; W3 = Wl3; b3p = bl3;
        pj2 = g_pj2l + b * NN * 64;
        u2base = g_u2l + (b * LL + l) * NN * 64;
    }

    const int g  = lane >> 2;     // 0..7
    const int q  = lane & 3;      // 0..3
    const int mg = wid & 1;       // m-half
    const int jg = wid >> 1;      // 0..3
    const int m0 = mg * 32;

    // ---- A fragments: W2T[m0..m0+31][:], fp16x2, once per block ----
    uint32_t af[2][8][4];
    #pragma unroll
    for (int mt = 0; mt < 2; mt++) {
        const int ra = m0 + mt * 16 + g;
        #pragma unroll
        for (int kt = 0; kt < 8; kt++) {
            const int k0 = kt * 16 + 2 * q;
            af[mt][kt][0] = h2u(
                __floats2half2_rn(W2[k0 * H2 + ra], W2[(k0 + 1) * H2 + ra]));
            af[mt][kt][1] = h2u(
                __floats2half2_rn(W2[k0 * H2 + ra + 8], W2[(k0 + 1) * H2 + ra + 8]));
            af[mt][kt][2] = h2u(
                __floats2half2_rn(W2[(k0 + 8) * H2 + ra], W2[(k0 + 9) * H2 + ra]));
            af[mt][kt][3] = h2u(
                __floats2half2_rn(W2[(k0 + 8) * H2 + ra + 8], W2[(k0 + 9) * H2 + ra + 8]));
        }
    }

    // epilogue per-thread constants
    float c2[2][2], w3[2][2];
    #pragma unroll
    for (int mt = 0; mt < 2; mt++) {
        const int ra = m0 + mt * 16 + g;
        c2[mt][0] = b2[ra];     w3[mt][0] = W3[ra];
        c2[mt][1] = b2[ra + 8]; w3[mt][1] = W3[ra + 8];
    }
    const float b3 = b3p[0];

    const __half2 hz = u2h(0u);
    const int kc = tid & 15;          // this thread's k-chunk (constant)
    const int jrow0 = tid >> 4;       // Phase A row base

    // ldmatrix lane-address offset (constant per thread)
    const uint32_t mi = (uint32_t)(lane >> 3);
    const uint32_t lmoff =
        (((uint32_t)(lane & 7) * ST) + (mi & 1) * 4 + (mi >> 1) * 8) * 4;

    auto phaseA = [&](int i, uint32_t* sh) {
        const uint4 uv = *(const uint4*)(u2base + i * 64 + kc * 4);
        const uint32_t* pjr = pj2 + jrow0 * 64 + kc * 4;
        uint32_t* shw = sh + jrow0 * ST + kc * 4;
        #pragma unroll
        for (int it = 0; it < 10; it++) {
            const uint4 pv = *(const uint4*)(pjr + it * 16 * 64);
            uint4 hv;
            hv.x = h2u(__hmax2(__hadd2(u2h(uv.x), u2h(pv.x)), hz));
            hv.y = h2u(__hmax2(__hadd2(u2h(uv.y), u2h(pv.y)), hz));
            hv.z = h2u(__hmax2(__hadd2(u2h(uv.z), u2h(pv.z)), hz));
            hv.w = h2u(__hmax2(__hadd2(u2h(uv.w), u2h(pv.w)), hz));
            *(uint4*)(shw + it * 16 * ST) = hv;
        }
    };

    phaseA(i0, s_h0);
    __syncthreads();

    #pragma unroll 1
    for (int ii = 0; ii < 4; ii++) {
        const int i = i0 + ii;
        uint32_t* sh = (ii & 1) ? s_h1 : s_h0;
        float* part = s_part + ii * 2 * NN;

        const uint32_t sh_b = (uint32_t)__cvta_generic_to_shared(sh) + lmoff;
        #pragma unroll 1
        for (int nt = 0; nt < 5; nt++) {
            const int n0 = jg * 40 + nt * 8;
            const uint32_t la = sh_b + (uint32_t)n0 * (ST * 4);

            // hoist all 4 ldmatrix.x4 — latencies overlap
            uint32_t bf[4][4];
            #pragma unroll
            for (int p = 0; p < 4; p++)
                ldmx4(bf[p][0], bf[p][1], bf[p][2], bf[p][3], la + p * 64);

            float d[2][4];
            #pragma unroll
            for (int mt = 0; mt < 2; mt++)
                d[mt][0] = d[mt][1] = d[mt][2] = d[mt][3] = 0.f;

            #pragma unroll
            for (int p = 0; p < 4; p++) {
                const int kt = 2 * p;
                mma_f16(d[0][0], d[0][1], d[0][2], d[0][3],
                        af[0][kt][0], af[0][kt][1], af[0][kt][2], af[0][kt][3],
                        bf[p][0], bf[p][1]);
                mma_f16(d[1][0], d[1][1], d[1][2], d[1][3],
                        af[1][kt][0], af[1][kt][1], af[1][kt][2], af[1][kt][3],
                        bf[p][0], bf[p][1]);
                mma_f16(d[0][0], d[0][1], d[0][2], d[0][3],
                        af[0][kt + 1][0], af[0][kt + 1][1], af[0][kt + 1][2], af[0][kt + 1][3],
                        bf[p][2], bf[p][3]);
                mma_f16(d[1][0], d[1][1], d[1][2], d[1][3],
                        af[1][kt + 1][0], af[1][kt + 1][1], af[1][kt + 1][2], af[1][kt + 1][3],
                        bf[p][2], bf[p][3]);
            }

            float p0 = 0.f, p1 = 0.f;
            #pragma unroll
            for (int mt = 0; mt < 2; mt++) {
                p0 += fmaxf(d[mt][0] + c2[mt][0], 0.f) * w3[mt][0]
                    + fmaxf(d[mt][2] + c2[mt][1], 0.f) * w3[mt][1];
                p1 += fmaxf(d[mt][1] + c2[mt][0], 0.f) * w3[mt][0]
                    + fmaxf(d[mt][3] + c2[mt][1], 0.f) * w3[mt][1];
            }
            p0 += __shfl_xor_sync(0xFFFFFFFFu, p0, 4);
            p0 += __shfl_xor_sync(0xFFFFFFFFu, p0, 8);
            p0 += __shfl_xor_sync(0xFFFFFFFFu, p0, 16);
            p1 += __shfl_xor_sync(0xFFFFFFFFu, p1, 4);
            p1 += __shfl_xor_sync(0xFFFFFFFFu, p1, 8);
            p1 += __shfl_xor_sync(0xFFFFFFFFu, p1, 16);
            if (g == 0) {
                part[mg * NN + n0 + 2 * q]     = p0;
                part[mg * NN + n0 + 2 * q + 1] = p1;
            }
        }

        // Phase A for next i into the other buffer (overlaps MMA pipes)
        if (ii < 3) phaseA(i0 + ii + 1, (ii & 1) ? s_h0 : s_h1);
        __syncthreads();

        // final: sum 2 mg partials, sigmoid, mask, store
        if (tid < NN) {
            const int j = tid;
            const float lg = b3 + part[j] + part[NN + j];
            float sig = 1.f / (1.f + __expf(-lg));
            if (i == j) sig = 0.f;
            size_t off;
            if (intra)
                off = ((size_t)(b * NN + i)) * NN + j;
            else
                off = (size_t)BB * NN * NN +
                      ((size_t)((b * LL + l) * NN) + i) * NN + j;
            out[off] = sig;
        }
    }
}

static const int PAIR_SMEM_BYTES =
    (2 * NN * ST) * (int)sizeof(uint32_t) + 4 * 2 * NN * (int)sizeof(float);

extern "C" void kernel_launch(void* const* d_in, const int* in_sizes, int n_in,
                              void* d_out, int out_size)
{
    const float* ne  = (const float*)d_in[0];
    const float* zi  = (const float*)d_in[1];
    const float* ze  = (const float*)d_in[2];
    const float* lag = (const float*)d_in[3];
    const float* Wi1 = (const float*)d_in[4];
    const float* bi1 = (const float*)d_in[5];
    const float* Wi2 = (const float*)d_in[6];
    const float* bi2 = (const float*)d_in[7];
    const float* Wi3 = (const float*)d_in[8];
    const float* bi3 = (const float*)d_in[9];
    const float* Wl1 = (const float*)d_in[10];
    const float* bl1 = (const float*)d_in[11];
    const float* Wl2 = (const float*)d_in[12];
    const float* bl2 = (const float*)d_in[13];
    const float* Wl3 = (const float*)d_in[14];
    const float* bl3 = (const float*)d_in[15];
    float* out = (float*)d_out;

    cudaFuncSetAttribute(pair_mma_kernel,
                         cudaFuncAttributeMaxDynamicSharedMemorySize,
                         PAIR_SMEM_BYTES);

    proj_kernel<<<BB * (NN / 4), H1>>>(ne, zi, ze, lag, Wi1, bi1, Wl1, bl1);

    const int nblocks = BB * (NN / 4) + BB * LL * (NN / 4);  // 800
    pair_mma_kernel<<<nblocks, 256, PAIR_SMEM_BYTES>>>(
        Wi2, bi2, Wi3, bi3, Wl2, bl2, Wl3, bl3, out);
}

// round 16
// speedup vs baseline: 1.0348x; 1.0348x over previous
#include <cuda_runtime.h>
#include <cuda_fp16.h>
#include <cstdint>

#define BB 4
#define NN 160
#define DD 64
#define ZIc 64
#define ZEc 64
#define LL 4
#define LEc 8
#define H1 128
#define H2 64
#define ST 68          // s_h row stride in 32-bit words (64 data + 4 pad)
#define NPROD 160      // producer blocks (= intra blocks)
#define NBLK 800

// ---------------- device scratch (allocation-free) ----------------
__device__ uint32_t g_u2i[BB * NN * 64];            // intra u  = pi + bi1 + pz
__device__ uint32_t g_pj2i[BB * NN * 64];           // intra pj
__device__ uint32_t g_pj2l[BB * NN * 64];           // inter pj (qj)
__device__ uint32_t g_u2l[BB * LL * NN * 64];       // inter u  = qi + qz + ql
__device__ int g_ready = 0;
__device__ int g_done  = 0;

__device__ __forceinline__ uint32_t h2u(__half2 h) {
    return *reinterpret_cast<uint32_t*>(&h);
}
__device__ __forceinline__ __half2 u2h(uint32_t u) {
    return *reinterpret_cast<__half2*>(&u);
}

__device__ __forceinline__ void mma_f16(float& d0, float& d1, float& d2, float& d3,
                                        uint32_t a0, uint32_t a1, uint32_t a2, uint32_t a3,
                                        uint32_t b0, uint32_t b1) {
    asm volatile(
        "mma.sync.aligned.m16n8k16.row.col.f32.f16.f16.f32 "
        "{%0,%1,%2,%3}, {%4,%5,%6,%7}, {%8,%9}, {%0,%1,%2,%3};"
        : "+f"(d0), "+f"(d1), "+f"(d2), "+f"(d3)
        : "r"(a0), "r"(a1), "r"(a2), "r"(a3), "r"(b0), "r"(b1));
}

__device__ __forceinline__ void ldmx4(uint32_t& r0, uint32_t& r1,
                                      uint32_t& r2, uint32_t& r3, uint32_t addr) {
    asm volatile(
        "ldmatrix.sync.aligned.m8n8.x4.shared.b16 {%0,%1,%2,%3}, [%4];"
        : "=r"(r0), "=r"(r1), "=r"(r2), "=r"(r3) : "r"(addr));
}

// ---------------------------------------------------------------------------
// Fused kernel: blocks 0..NPROD-1 produce projections, all 800 blocks then
// run the fp16 mma pairwise MLP after an acquire-spin on g_ready.
// ---------------------------------------------------------------------------
extern __shared__ uint32_t smemw[];

__global__ __launch_bounds__(256, 2) void fused_kernel(
    const float* __restrict__ ne,  const float* __restrict__ zi,
    const float* __restrict__ ze,  const float* __restrict__ lag,
    const float* __restrict__ Wi1, const float* __restrict__ bi1,
    const float* __restrict__ Wi2, const float* __restrict__ bi2,
    const float* __restrict__ Wi3, const float* __restrict__ bi3,
    const float* __restrict__ Wl1, const float* __restrict__ bl1,
    const float* __restrict__ Wl2, const float* __restrict__ bl2,
    const float* __restrict__ Wl3, const float* __restrict__ bl3,
    float* __restrict__ out)
{
    const int tid  = threadIdx.x;
    const int wid  = tid >> 5;
    const int lane = tid & 31;
    const int bid  = blockIdx.x;

    // ================= producer section (blocks 0..159) =================
    if (bid < NPROD) {
        // overlay proj scratch on the (not yet used) pair smem
        float* s_ne   = (float*)smemw;          // 4*DD
        float* s_zi   = s_ne + 4 * DD;          // ZIc
        float* s_ze   = s_zi + ZIc;             // ZEc
        float* s_pack = s_ze + ZEc;             // 4*7*H1

        const int b  = bid / (NN / 4);
        const int n0 = (bid % (NN / 4)) * 4;

        for (int t = tid; t < 4 * DD; t += 256)
            s_ne[t] = ne[(b * NN + n0 + (t >> 6)) * DD + (t & 63)];
        if (tid < ZIc) s_zi[tid] = zi[b * ZIc + tid];
        else if (tid >= 128 && tid < 128 + ZEc) s_ze[tid - 128] = ze[b * ZEc + (tid - 128)];
        __syncthreads();

        if (tid < H1) {
            const int k = tid;
            float api[4], apj[4], aqi[4], aqj[4];
            #pragma unroll
            for (int n = 0; n < 4; n++) { api[n] = apj[n] = aqi[n] = aqj[n] = 0.f; }

            #pragma unroll 4
            for (int d = 0; d < DD; d++) {
                const float wa = Wi1[d * H1 + k];
                const float wb = Wi1[(DD + d) * H1 + k];
                const float va = Wl1[d * H1 + k];
                const float vb = Wl1[(DD + d) * H1 + k];
                #pragma unroll
                for (int n = 0; n < 4; n++) {
                    const float nd = s_ne[n * DD + d];
                    api[n] += nd * wa;
                    apj[n] += nd * wb;
                    aqi[n] += nd * va;
                    aqj[n] += nd * vb;
                }
            }

            float pz = bi1[k], qz = bl1[k];
            #pragma unroll 4
            for (int z = 0; z < ZIc; z++) {
                pz += s_zi[z] * Wi1[(2 * DD + z) * H1 + k];
                qz += s_ze[z] * Wl1[(2 * DD + z) * H1 + k];
            }

            float ql[LL];
            #pragma unroll
            for (int l = 0; l < LL; l++) {
                float a = 0.f;
                #pragma unroll
                for (int e = 0; e < LEc; e++)
                    a += lag[l * LEc + e] * Wl1[(2 * DD + ZEc + e) * H1 + k];
                ql[l] = a;
            }

            #pragma unroll
            for (int n = 0; n < 4; n++) {
                s_pack[(n * 7 + 0) * H1 + k] = api[n] + pz;
                s_pack[(n * 7 + 1) * H1 + k] = apj[n];
                s_pack[(n * 7 + 2) * H1 + k] = aqj[n];
                #pragma unroll
                for (int l = 0; l < LL; l++)
                    s_pack[(n * 7 + 3 + l) * H1 + k] = aqi[n] + qz + ql[l];
            }
        }
        __syncthreads();

        for (int idx = tid; idx < 4 * 7 * 64; idx += 256) {
            const int n   = idx / (7 * 64);
            const int row = (idx >> 6) % 7;
            const int c   = idx & 63;
            const int gn  = b * NN + n0 + n;
            const uint32_t v = h2u(__floats2half2_rn(
                s_pack[(n * 7 + row) * H1 + 2 * c],
                s_pack[(n * 7 + row) * H1 + 2 * c + 1]));
            if (row == 0)      g_u2i[gn * 64 + c] = v;
            else if (row == 1) g_pj2i[gn * 64 + c] = v;
            else if (row == 2) g_pj2l[gn * 64 + c] = v;
            else               g_u2l[((b * LL + (row - 3)) * NN + (n0 + n)) * 64 + c] = v;
        }
        __threadfence();
        __syncthreads();
        if (tid == 0) atomicAdd(&g_ready, 1);
    }

    // ================= pair setup (all blocks; overlaps others' proj) ====
    const bool intra = (bid < NPROD);
    int b, l = 0, i0;
    const float *W2, *b2, *W3, *b3p;
    const uint32_t *pj2, *u2base;
    if (intra) {
        b  = bid / (NN / 4);
        i0 = (bid % (NN / 4)) * 4;
        W2 = Wi2; b2 = bi2; W3 = Wi3; b3p = bi3;
        pj2 = g_pj2i + b * NN * 64;
        u2base = g_u2i + b * NN * 64;
    } else {
        const int e = bid - NPROD;
        b = e / (LL * (NN / 4));
        const int r = e % (LL * (NN / 4));
        l  = r / (NN / 4);
        i0 = (r % (NN / 4)) * 4;
        W2 = Wl2; b2 = bl2; W3 = Wl3; b3p = bl3;
        pj2 = g_pj2l + b * NN * 64;
        u2base = g_u2l + (b * LL + l) * NN * 64;
    }

    const int g  = lane >> 2;
    const int q  = lane & 3;
    const int mg = wid & 1;
    const int jg = wid >> 1;
    const int m0 = mg * 32;

    // A fragments: W2T[m0..m0+31][:], fp16x2 (independent of proj output)
    uint32_t af[2][8][4];
    #pragma unroll
    for (int mt = 0; mt < 2; mt++) {
        const int ra = m0 + mt * 16 + g;
        #pragma unroll
        for (int kt = 0; kt < 8; kt++) {
            const int k0 = kt * 16 + 2 * q;
            af[mt][kt][0] = h2u(
                __floats2half2_rn(W2[k0 * H2 + ra], W2[(k0 + 1) * H2 + ra]));
            af[mt][kt][1] = h2u(
                __floats2half2_rn(W2[k0 * H2 + ra + 8], W2[(k0 + 1) * H2 + ra + 8]));
            af[mt][kt][2] = h2u(
                __floats2half2_rn(W2[(k0 + 8) * H2 + ra], W2[(k0 + 9) * H2 + ra]));
            af[mt][kt][3] = h2u(
                __floats2half2_rn(W2[(k0 + 8) * H2 + ra + 8], W2[(k0 + 9) * H2 + ra + 8]));
        }
    }

    float c2[2][2], w3[2][2];
    #pragma unroll
    for (int mt = 0; mt < 2; mt++) {
        const int ra = m0 + mt * 16 + g;
        c2[mt][0] = b2[ra];     w3[mt][0] = W3[ra];
        c2[mt][1] = b2[ra + 8]; w3[mt][1] = W3[ra + 8];
    }
    const float b3 = b3p[0];

    // ---- acquire-spin until all producers signalled ----
    if (tid == 0) {
        int r;
        while (true) {
            asm volatile("ld.acquire.gpu.s32 %0, [%1];"
                         : "=r"(r) : "l"(&g_ready) : "memory");
            if (r >= NPROD) break;
            __nanosleep(64);
        }
    }
    __syncthreads();

    // ================= pair compute =================
    uint32_t* s_h0   = smemw;
    uint32_t* s_h1   = smemw + NN * ST;
    float*    s_part = (float*)(smemw + 2 * NN * ST);

    const __half2 hz = u2h(0u);
    const int kc = tid & 15;
    const int jrow0 = tid >> 4;

    const uint32_t mi = (uint32_t)(lane >> 3);
    const uint32_t lmoff =
        (((uint32_t)(lane & 7) * ST) + (mi & 1) * 4 + (mi >> 1) * 8) * 4;

    auto phaseA = [&](int i, uint32_t* sh) {
        const uint4 uv = *(const uint4*)(u2base + i * 64 + kc * 4);
        const uint32_t* pjr = pj2 + jrow0 * 64 + kc * 4;
        uint32_t* shw = sh + jrow0 * ST + kc * 4;
        #pragma unroll
        for (int it = 0; it < 10; it++) {
            const uint4 pv = *(const uint4*)(pjr + it * 16 * 64);
            uint4 hv;
            hv.x = h2u(__hmax2(__hadd2(u2h(uv.x), u2h(pv.x)), hz));
            hv.y = h2u(__hmax2(__hadd2(u2h(uv.y), u2h(pv.y)), hz));
            hv.z = h2u(__hmax2(__hadd2(u2h(uv.z), u2h(pv.z)), hz));
            hv.w = h2u(__hmax2(__hadd2(u2h(uv.w), u2h(pv.w)), hz));
            *(uint4*)(shw + it * 16 * ST) = hv;
        }
    };

    phaseA(i0, s_h0);
    __syncthreads();

    #pragma unroll 1
    for (int ii = 0; ii < 4; ii++) {
        const int i = i0 + ii;
        uint32_t* sh = (ii & 1) ? s_h1 : s_h0;
        float* part = s_part + ii * 2 * NN;

        const uint32_t sh_b = (uint32_t)__cvta_generic_to_shared(sh) + lmoff;
        #pragma unroll 1
        for (int nt = 0; nt < 5; nt++) {
            const int n0 = jg * 40 + nt * 8;
            const uint32_t la = sh_b + (uint32_t)n0 * (ST * 4);

            uint32_t bf[4][4];
            #pragma unroll
            for (int p = 0; p < 4; p++)
                ldmx4(bf[p][0], bf[p][1], bf[p][2], bf[p][3], la + p * 64);

            float d[2][4];
            #pragma unroll
            for (int mt = 0; mt < 2; mt++)
                d[mt][0] = d[mt][1] = d[mt][2] = d[mt][3] = 0.f;

            #pragma unroll
            for (int p = 0; p < 4; p++) {
                const int kt = 2 * p;
                mma_f16(d[0][0], d[0][1], d[0][2], d[0][3],
                        af[0][kt][0], af[0][kt][1], af[0][kt][2], af[0][kt][3],
                        bf[p][0], bf[p][1]);
                mma_f16(d[1][0], d[1][1], d[1][2], d[1][3],
                        af[1][kt][0], af[1][kt][1], af[1][kt][2], af[1][kt][3],
                        bf[p][0], bf[p][1]);
                mma_f16(d[0][0], d[0][1], d[0][2], d[0][3],
                        af[0][kt + 1][0], af[0][kt + 1][1], af[0][kt + 1][2], af[0][kt + 1][3],
                        bf[p][2], bf[p][3]);
                mma_f16(d[1][0], d[1][1], d[1][2], d[1][3],
                        af[1][kt + 1][0], af[1][kt + 1][1], af[1][kt + 1][2], af[1][kt + 1][3],
                        bf[p][2], bf[p][3]);
            }

            float p0 = 0.f, p1 = 0.f;
            #pragma unroll
            for (int mt = 0; mt < 2; mt++) {
                p0 += fmaxf(d[mt][0] + c2[mt][0], 0.f) * w3[mt][0]
                    + fmaxf(d[mt][2] + c2[mt][1], 0.f) * w3[mt][1];
                p1 += fmaxf(d[mt][1] + c2[mt][0], 0.f) * w3[mt][0]
                    + fmaxf(d[mt][3] + c2[mt][1], 0.f) * w3[mt][1];
            }
            p0 += __shfl_xor_sync(0xFFFFFFFFu, p0, 4);
            p0 += __shfl_xor_sync(0xFFFFFFFFu, p0, 8);
            p0 += __shfl_xor_sync(0xFFFFFFFFu, p0, 16);
            p1 += __shfl_xor_sync(0xFFFFFFFFu, p1, 4);
            p1 += __shfl_xor_sync(0xFFFFFFFFu, p1, 8);
            p1 += __shfl_xor_sync(0xFFFFFFFFu, p1, 16);
            if (g == 0) {
                part[mg * NN + n0 + 2 * q]     = p0;
                part[mg * NN + n0 + 2 * q + 1] = p1;
            }
        }

        if (ii < 3) phaseA(i0 + ii + 1, (ii & 1) ? s_h0 : s_h1);
        __syncthreads();

        if (tid < NN) {
            const int j = tid;
            const float lg = b3 + part[j] + part[NN + j];
            float sig = 1.f / (1.f + __expf(-lg));
            if (i == j) sig = 0.f;
            size_t off;
            if (intra)
                off = ((size_t)(b * NN + i)) * NN + j;
            else
                off = (size_t)BB * NN * NN +
                      ((size_t)((b * LL + l) * NN) + i) * NN + j;
            out[off] = sig;
        }
    }

    // ---- replay-safe counter reset ----
    __syncthreads();
    if (tid == 0) {
        const int d = atomicAdd(&g_done, 1);
        if (d == NBLK - 1) {
            g_ready = 0;
            g_done  = 0;
            __threadfence();
        }
    }
}

static const int FUSED_SMEM_BYTES =
    (2 * NN * ST) * (int)sizeof(uint32_t) + 4 * 2 * NN * (int)sizeof(float);

extern "C" void kernel_launch(void* const* d_in, const int* in_sizes, int n_in,
                              void* d_out, int out_size)
{
    const float* ne  = (const float*)d_in[0];
    const float* zi  = (const float*)d_in[1];
    const float* ze  = (const float*)d_in[2];
    const float* lag = (const float*)d_in[3];
    const float* Wi1 = (const float*)d_in[4];
    const float* bi1 = (const float*)d_in[5];
    const float* Wi2 = (const float*)d_in[6];
    const float* bi2 = (const float*)d_in[7];
    const float* Wi3 = (const float*)d_in[8];
    const float* bi3 = (const float*)d_in[9];
    const float* Wl1 = (const float*)d_in[10];
    const float* bl1 = (const float*)d_in[11];
    const float* Wl2 = (const float*)d_in[12];
    const float* bl2 = (const float*)d_in[13];
    const float* Wl3 = (const float*)d_in[14];
    const float* bl3 = (const float*)d_in[15];
    float* out = (float*)d_out;

    cudaFuncSetAttribute(fused_kernel,
                         cudaFuncAttributeMaxDynamicSharedMemorySize,
                         FUSED_SMEM_BYTES);

    fused_kernel<<<NBLK, 256, FUSED_SMEM_BYTES>>>(
        ne, zi, ze, lag, Wi1, bi1, Wi2, bi2, Wi3, bi3,
        Wl1, bl1, Wl2, bl2, Wl3, bl3, out);
}

// round 17
// speedup vs baseline: 1.0680x; 1.0321x over previous
#include <cuda_runtime.h>
#include <cuda_fp16.h>
#include <cstdint>

#define BB 4
#define NN 160
#define DD 64
#define ZIc 64
#define ZEc 64
#define LL 4
#define LEc 8
#define H1 128
#define H2 64
#define ST 68          // s_h row stride in 32-bit words (64 data + 4 pad)
#define PS 168         // part row stride in floats (mod 32 == 8 -> <=2-way STS)
#define NPROD 160      // producer blocks (= intra blocks)
#define NBLK 800

// ---------------- device scratch (allocation-free) ----------------
__device__ uint32_t g_u2i[BB * NN * 64];            // intra u  = pi + bi1 + pz
__device__ uint32_t g_pj2i[BB * NN * 64];           // intra pj
__device__ uint32_t g_pj2l[BB * NN * 64];           // inter pj (qj)
__device__ uint32_t g_u2l[BB * LL * NN * 64];       // inter u  = qi + qz + ql
__device__ int g_readyB[BB] = {0, 0, 0, 0};
__device__ int g_done  = 0;

__device__ __forceinline__ uint32_t h2u(__half2 h) {
    return *reinterpret_cast<uint32_t*>(&h);
}
__device__ __forceinline__ __half2 u2h(uint32_t u) {
    return *reinterpret_cast<__half2*>(&u);
}

__device__ __forceinline__ void mma_f16(float& d0, float& d1, float& d2, float& d3,
                                        uint32_t a0, uint32_t a1, uint32_t a2, uint32_t a3,
                                        uint32_t b0, uint32_t b1) {
    asm volatile(
        "mma.sync.aligned.m16n8k16.row.col.f32.f16.f16.f32 "
        "{%0,%1,%2,%3}, {%4,%5,%6,%7}, {%8,%9}, {%0,%1,%2,%3};"
        : "+f"(d0), "+f"(d1), "+f"(d2), "+f"(d3)
        : "r"(a0), "r"(a1), "r"(a2), "r"(a3), "r"(b0), "r"(b1));
}

__device__ __forceinline__ void ldmx4(uint32_t& r0, uint32_t& r1,
                                      uint32_t& r2, uint32_t& r3, uint32_t addr) {
    asm volatile(
        "ldmatrix.sync.aligned.m8n8.x4.shared.b16 {%0,%1,%2,%3}, [%4];"
        : "=r"(r0), "=r"(r1), "=r"(r2), "=r"(r3) : "r"(addr));
}

// ---------------------------------------------------------------------------
// Fused kernel: blocks 0..NPROD-1 produce projections for their batch b,
// all 800 blocks then run the fp16 mma pairwise MLP after an acquire-spin
// on their batch's ready counter. Epilogue uses STS partials (no shfl).
// ---------------------------------------------------------------------------
extern __shared__ uint32_t smemw[];

__global__ __launch_bounds__(256, 2) void fused_kernel(
    const float* __restrict__ ne,  const float* __restrict__ zi,
    const float* __restrict__ ze,  const float* __restrict__ lag,
    const float* __restrict__ Wi1, const float* __restrict__ bi1,
    const float* __restrict__ Wi2, const float* __restrict__ bi2,
    const float* __restrict__ Wi3, const float* __restrict__ bi3,
    const float* __restrict__ Wl1, const float* __restrict__ bl1,
    const float* __restrict__ Wl2, const float* __restrict__ bl2,
    const float* __restrict__ Wl3, const float* __restrict__ bl3,
    float* __restrict__ out)
{
    const int tid  = threadIdx.x;
    const int wid  = tid >> 5;
    const int lane = tid & 31;
    const int bid  = blockIdx.x;

    // ================= producer section (blocks 0..159) =================
    if (bid < NPROD) {
        float* s_ne   = (float*)smemw;          // 4*DD
        float* s_zi   = s_ne + 4 * DD;          // ZIc
        float* s_ze   = s_zi + ZIc;             // ZEc
        float* s_pack = s_ze + ZEc;             // 4*7*H1

        const int b  = bid / (NN / 4);
        const int n0 = (bid % (NN / 4)) * 4;

        for (int t = tid; t < 4 * DD; t += 256)
            s_ne[t] = ne[(b * NN + n0 + (t >> 6)) * DD + (t & 63)];
        if (tid < ZIc) s_zi[tid] = zi[b * ZIc + tid];
        else if (tid >= 128 && tid < 128 + ZEc) s_ze[tid - 128] = ze[b * ZEc + (tid - 128)];
        __syncthreads();

        if (tid < H1) {
            const int k = tid;
            float api[4], apj[4], aqi[4], aqj[4];
            #pragma unroll
            for (int n = 0; n < 4; n++) { api[n] = apj[n] = aqi[n] = aqj[n] = 0.f; }

            #pragma unroll 4
            for (int d = 0; d < DD; d++) {
                const float wa = Wi1[d * H1 + k];
                const float wb = Wi1[(DD + d) * H1 + k];
                const float va = Wl1[d * H1 + k];
                const float vb = Wl1[(DD + d) * H1 + k];
                #pragma unroll
                for (int n = 0; n < 4; n++) {
                    const float nd = s_ne[n * DD + d];
                    api[n] += nd * wa;
                    apj[n] += nd * wb;
                    aqi[n] += nd * va;
                    aqj[n] += nd * vb;
                }
            }

            float pz = bi1[k], qz = bl1[k];
            #pragma unroll 4
            for (int z = 0; z < ZIc; z++) {
                pz += s_zi[z] * Wi1[(2 * DD + z) * H1 + k];
                qz += s_ze[z] * Wl1[(2 * DD + z) * H1 + k];
            }

            float ql[LL];
            #pragma unroll
            for (int l = 0; l < LL; l++) {
                float a = 0.f;
                #pragma unroll
                for (int e = 0; e < LEc; e++)
                    a += lag[l * LEc + e] * Wl1[(2 * DD + ZEc + e) * H1 + k];
                ql[l] = a;
            }

            #pragma unroll
            for (int n = 0; n < 4; n++) {
                s_pack[(n * 7 + 0) * H1 + k] = api[n] + pz;
                s_pack[(n * 7 + 1) * H1 + k] = apj[n];
                s_pack[(n * 7 + 2) * H1 + k] = aqj[n];
                #pragma unroll
                for (int l = 0; l < LL; l++)
                    s_pack[(n * 7 + 3 + l) * H1 + k] = aqi[n] + qz + ql[l];
            }
        }
        __syncthreads();

        for (int idx = tid; idx < 4 * 7 * 64; idx += 256) {
            const int n   = idx / (7 * 64);
            const int row = (idx >> 6) % 7;
            const int c   = idx & 63;
            const int gn  = b * NN + n0 + n;
            const uint32_t v = h2u(__floats2half2_rn(
                s_pack[(n * 7 + row) * H1 + 2 * c],
                s_pack[(n * 7 + row) * H1 + 2 * c + 1]));
            if (row == 0)      g_u2i[gn * 64 + c] = v;
            else if (row == 1) g_pj2i[gn * 64 + c] = v;
            else if (row == 2) g_pj2l[gn * 64 + c] = v;
            else               g_u2l[((b * LL + (row - 3)) * NN + (n0 + n)) * 64 + c] = v;
        }
        __threadfence();
        __syncthreads();
        if (tid == 0) atomicAdd(&g_readyB[b], 1);
    }

    // ================= pair setup (all blocks; overlaps others' proj) ====
    const bool intra = (bid < NPROD);
    int b, l = 0, i0;
    const float *W2, *b2, *W3, *b3p;
    const uint32_t *pj2, *u2base;
    if (intra) {
        b  = bid / (NN / 4);
        i0 = (bid % (NN / 4)) * 4;
        W2 = Wi2; b2 = bi2; W3 = Wi3; b3p = bi3;
        pj2 = g_pj2i + b * NN * 64;
        u2base = g_u2i + b * NN * 64;
    } else {
        const int e = bid - NPROD;
        b = e / (LL * (NN / 4));
        const int r = e % (LL * (NN / 4));
        l  = r / (NN / 4);
        i0 = (r % (NN / 4)) * 4;
        W2 = Wl2; b2 = bl2; W3 = Wl3; b3p = bl3;
        pj2 = g_pj2l + b * NN * 64;
        u2base = g_u2l + (b * LL + l) * NN * 64;
    }

    const int g  = lane >> 2;
    const int q  = lane & 3;
    const int mg = wid & 1;
    const int jg = wid >> 1;
    const int m0 = mg * 32;

    // A fragments: W2T[m0..m0+31][:], fp16x2 (independent of proj output)
    uint32_t af[2][8][4];
    #pragma unroll
    for (int mt = 0; mt < 2; mt++) {
        const int ra = m0 + mt * 16 + g;
        #pragma unroll
        for (int kt = 0; kt < 8; kt++) {
            const int k0 = kt * 16 + 2 * q;
            af[mt][kt][0] = h2u(
                __floats2half2_rn(W2[k0 * H2 + ra], W2[(k0 + 1) * H2 + ra]));
            af[mt][kt][1] = h2u(
                __floats2half2_rn(W2[k0 * H2 + ra + 8], W2[(k0 + 1) * H2 + ra + 8]));
            af[mt][kt][2] = h2u(
                __floats2half2_rn(W2[(k0 + 8) * H2 + ra], W2[(k0 + 9) * H2 + ra]));
            af[mt][kt][3] = h2u(
                __floats2half2_rn(W2[(k0 + 8) * H2 + ra + 8], W2[(k0 + 9) * H2 + ra + 8]));
        }
    }

    float c2[2][2], w3[2][2];
    #pragma unroll
    for (int mt = 0; mt < 2; mt++) {
        const int ra = m0 + mt * 16 + g;
        c2[mt][0] = b2[ra];     w3[mt][0] = W3[ra];
        c2[mt][1] = b2[ra + 8]; w3[mt][1] = W3[ra + 8];
    }
    const float b3 = b3p[0];

    // ---- acquire-spin until this batch's producers signalled ----
    if (tid == 0) {
        int r;
        while (true) {
            asm volatile("ld.acquire.gpu.s32 %0, [%1];"
                         : "=r"(r) : "l"(&g_readyB[b]) : "memory");
            if (r >= NN / 4) break;
            __nanosleep(64);
        }
    }
    __syncthreads();

    // ================= pair compute =================
    uint32_t* s_h0   = smemw;                       // NN*ST
    uint32_t* s_h1   = smemw + NN * ST;             // NN*ST
    float*    s_part = (float*)(smemw + 2 * NN * ST);  // [2 buf][16][PS]

    const __half2 hz = u2h(0u);
    const int kc = tid & 15;
    const int jrow0 = tid >> 4;

    const uint32_t mi = (uint32_t)(lane >> 3);
    const uint32_t lmoff =
        (((uint32_t)(lane & 7) * ST) + (mi & 1) * 4 + (mi >> 1) * 8) * 4;

    auto phaseA = [&](int i, uint32_t* sh) {
        const uint4 uv = *(const uint4*)(u2base + i * 64 + kc * 4);
        const uint32_t* pjr = pj2 + jrow0 * 64 + kc * 4;
        uint32_t* shw = sh + jrow0 * ST + kc * 4;
        #pragma unroll
        for (int it = 0; it < 10; it++) {
            const uint4 pv = *(const uint4*)(pjr + it * 16 * 64);
            uint4 hv;
            hv.x = h2u(__hmax2(__hadd2(u2h(uv.x), u2h(pv.x)), hz));
            hv.y = h2u(__hmax2(__hadd2(u2h(uv.y), u2h(pv.y)), hz));
            hv.z = h2u(__hmax2(__hadd2(u2h(uv.z), u2h(pv.z)), hz));
            hv.w = h2u(__hmax2(__hadd2(u2h(uv.w), u2h(pv.w)), hz));
            *(uint4*)(shw + it * 16 * ST) = hv;
        }
    };

    phaseA(i0, s_h0);
    __syncthreads();

    #pragma unroll 1
    for (int ii = 0; ii < 4; ii++) {
        const int i = i0 + ii;
        uint32_t* sh = (ii & 1) ? s_h1 : s_h0;
        float* part = s_part + (ii & 1) * 16 * PS;
        // this thread's partial slot: row mg*8+g
        float* prow = part + (mg * 8 + g) * PS;

        const uint32_t sh_b = (uint32_t)__cvta_generic_to_shared(sh) + lmoff;
        #pragma unroll 1
        for (int nt = 0; nt < 5; nt++) {
            const int n0 = jg * 40 + nt * 8;
            const uint32_t la = sh_b + (uint32_t)n0 * (ST * 4);

            uint32_t bf[4][4];
            #pragma unroll
            for (int p = 0; p < 4; p++)
                ldmx4(bf[p][0], bf[p][1], bf[p][2], bf[p][3], la + p * 64);

            float d[2][4];
            #pragma unroll
            for (int mt = 0; mt < 2; mt++)
                d[mt][0] = d[mt][1] = d[mt][2] = d[mt][3] = 0.f;

            #pragma unroll
            for (int p = 0; p < 4; p++) {
                const int kt = 2 * p;
                mma_f16(d[0][0], d[0][1], d[0][2], d[0][3],
                        af[0][kt][0], af[0][kt][1], af[0][kt][2], af[0][kt][3],
                        bf[p][0], bf[p][1]);
                mma_f16(d[1][0], d[1][1], d[1][2], d[1][3],
                        af[1][kt][0], af[1][kt][1], af[1][kt][2], af[1][kt][3],
                        bf[p][0], bf[p][1]);
                mma_f16(d[0][0], d[0][1], d[0][2], d[0][3],
                        af[0][kt + 1][0], af[0][kt + 1][1], af[0][kt + 1][2], af[0][kt + 1][3],
                        bf[p][2], bf[p][3]);
                mma_f16(d[1][0], d[1][1], d[1][2], d[1][3],
                        af[1][kt + 1][0], af[1][kt + 1][1], af[1][kt + 1][2], af[1][kt + 1][3],
                        bf[p][2], bf[p][3]);
            }

            // relu(d + b2)*W3 for this thread's 2 m-rows; STS per-lane partials
            float p0 = 0.f, p1 = 0.f;
            #pragma unroll
            for (int mt = 0; mt < 2; mt++) {
                p0 += fmaxf(d[mt][0] + c2[mt][0], 0.f) * w3[mt][0]
                    + fmaxf(d[mt][2] + c2[mt][1], 0.f) * w3[mt][1];
                p1 += fmaxf(d[mt][1] + c2[mt][0], 0.f) * w3[mt][0]
                    + fmaxf(d[mt][3] + c2[mt][1], 0.f) * w3[mt][1];
            }
            prow[n0 + 2 * q]     = p0;
            prow[n0 + 2 * q + 1] = p1;
        }

        if (ii < 3) phaseA(i0 + ii + 1, (ii & 1) ? s_h0 : s_h1);
        __syncthreads();

        // final: sum 16 partial rows, sigmoid, mask, store
        if (tid < NN) {
            const int j = tid;
            float lg = b3;
            #pragma unroll
            for (int r = 0; r < 16; r++) lg += part[r * PS + j];
            float sig = 1.f / (1.f + __expf(-lg));
            if (i == j) sig = 0.f;
            size_t off;
            if (intra)
                off = ((size_t)(b * NN + i)) * NN + j;
            else
                off = (size_t)BB * NN * NN +
                      ((size_t)((b * LL + l) * NN) + i) * NN + j;
            out[off] = sig;
        }
    }

    // ---- replay-safe counter reset ----
    __syncthreads();
    if (tid == 0) {
        const int d = atomicAdd(&g_done, 1);
        if (d == NBLK - 1) {
            #pragma unroll
            for (int bb = 0; bb < BB; bb++) g_readyB[bb] = 0;
            g_done = 0;
            __threadfence();
        }
    }
}

static const int FUSED_SMEM_BYTES =
    (2 * NN * ST) * (int)sizeof(uint32_t) + 2 * 16 * PS * (int)sizeof(float);

extern "C" void kernel_launch(void* const* d_in, const int* in_sizes, int n_in,
                              void* d_out, int out_size)
{
    const float* ne  = (const float*)d_in[0];
    const float* zi  = (const float*)d_in[1];
    const float* ze  = (const float*)d_in[2];
    const float* lag = (const float*)d_in[3];
    const float* Wi1 = (const float*)d_in[4];
    const float* bi1 = (const float*)d_in[5];
    const float* Wi2 = (const float*)d_in[6];
    const float* bi2 = (const float*)d_in[7];
    const float* Wi3 = (const float*)d_in[8];
    const float* bi3 = (const float*)d_in[9];
    const float* Wl1 = (const float*)d_in[10];
    const float* bl1 = (const float*)d_in[11];
    const float* Wl2 = (const float*)d_in[12];
    const float* bl2 = (const float*)d_in[13];
    const float* Wl3 = (const float*)d_in[14];
    const float* bl3 = (const float*)d_in[15];
    float* out = (float*)d_out;

    cudaFuncSetAttribute(fused_kernel,
                         cudaFuncAttributeMaxDynamicSharedMemorySize,
                         FUSED_SMEM_BYTES);

    fused_kernel<<<NBLK, 256, FUSED_SMEM_BYTES>>>(
        ne, zi, ze, lag, Wi1, bi1, Wi2, bi2, Wi3, bi3,
        Wl1, bl1, Wl2, bl2, Wl3, bl3, out);
}